// round 11
// baseline (speedup 1.0000x reference)
#include <cuda_runtime.h>
#include <cstdint>

#define NB   32
#define NH   64
#define NW   64
#define HO   62
#define WO   62
#define NPB  (HO*WO)            // 3844

// A: [g 12][ocg 2][kw 3][oc 64][slot 8] fp16x2
__device__ __align__(16) uint32_t g_a16[36864];              // 147.5 KB

// ---- SMEM geometry (words per buffer) ----
#define AWRD  1536              // 3 kw tiles x 64 oc x 8 slots
#define BWRD  1088              // 8 c2 x 2 rows x 68
#define STW   (AWRD + BWRD)     // 2624
#define NBUF  3                 // 31488 B static

// ---------------- PTX helpers ----------------
__device__ __forceinline__ uint32_t cvta_s(const void* p) {
    uint32_t a;
    asm("{ .reg .u64 t; cvta.to.shared.u64 t, %1; cvt.u32.u64 %0, t; }" : "=r"(a) : "l"(p));
    return a;
}
__device__ __forceinline__ uint32_t pack_h2(float even, float odd) {
    uint32_t d;
    asm("cvt.rn.f16x2.f32 %0, %1, %2;" : "=r"(d) : "f"(odd), "f"(even));  // lo=even, hi=odd
    return d;
}
__device__ __forceinline__ uint2 lds64(uint32_t addr) {
    uint2 v;
    asm volatile("ld.shared.v2.b32 {%0,%1},[%2];" : "=r"(v.x), "=r"(v.y) : "r"(addr));
    return v;
}
__device__ __forceinline__ uint32_t lds32(uint32_t addr) {
    uint32_t v;
    asm volatile("ld.shared.b32 %0,[%1];" : "=r"(v) : "r"(addr));
    return v;
}
__device__ __forceinline__ void sts128(uint32_t addr, uint4 v) {
    asm volatile("st.shared.v4.b32 [%0],{%1,%2,%3,%4};"
                 :: "r"(addr), "r"(v.x), "r"(v.y), "r"(v.z), "r"(v.w) : "memory");
}
#define CP_A16(dst, src) asm volatile("cp.async.cg.shared.global [%0],[%1],16;" :: "r"(dst), "l"(src))
#define CP_COMMIT()      asm volatile("cp.async.commit_group;" ::: "memory")
#define CP_WAIT0()       asm volatile("cp.async.wait_group 0;" ::: "memory")
#define CP_WAIT1()       asm volatile("cp.async.wait_group 1;" ::: "memory")

__device__ __forceinline__ void mma_f16(float* c, const uint32_t* a, const uint32_t* b) {
    asm volatile(
        "mma.sync.aligned.m16n8k16.row.col.f32.f16.f16.f32 "
        "{%0,%1,%2,%3},{%4,%5,%6,%7},{%8,%9},{%0,%1,%2,%3};"
        : "+f"(c[0]), "+f"(c[1]), "+f"(c[2]), "+f"(c[3])
        : "r"(a[0]), "r"(a[1]), "r"(a[2]), "r"(a[3]), "r"(b[0]), "r"(b[1]));
}

// ---------------- prep kernel (weights only) ----------------
// layout: idx = ((((g*2 + ocg)*3 + kw)*64 + oc)*8 + slot)
__global__ void prep_w(const float* __restrict__ w) {
    int idx = blockIdx.x * 256 + threadIdx.x;    // 36864
    int slot = idx & 7;
    int r    = idx >> 3;
    int oc   = r & 63;  r >>= 6;
    int kw   = r % 3;   r /= 3;
    int ocg  = r & 1;
    int g    = r >> 1;
    int kh   = g >> 2;
    int cblk = g & 3;
    int off  = kh * 3 + kw;
    int p    = (slot >> 1) + 4 * (slot & 1);
    int ce   = cblk * 16 + 2 * p;
    int oco  = ocg * 64 + oc;
    g_a16[idx] = pack_h2(w[oco * 576 + ce * 9 + off], w[oco * 576 + (ce + 1) * 9 + off]);
}

// ---------------- main kernel ----------------
// CTA: 64 oc x 2 rows x 64 wo. 8 warps = 2 oc-halves x 2 rows x 2 wo-halves.
__global__ __launch_bounds__(256, 3) void conv_main(const float* __restrict__ x,
                                                    float* __restrict__ out) {
    __shared__ __align__(16) uint32_t sm[NBUF * STW];    // 31488 B

    const int tid  = threadIdx.x;
    const int lane = tid & 31;
    const int warp = tid >> 5;
    const int woc  = warp >> 2;        // 0..1 : oc half within CTA (32 oc)
    const int wn   = warp & 3;
    const int rW   = wn >> 1;          // output row within pair
    const int cW   = (wn & 1) * 32;    // wo base

    const int b   = blockIdx.y;
    const int ocg = blockIdx.x & 1;    // 0..1 : 64-oc group
    const int ho0 = (blockIdx.x >> 1) * 2;

    const uint32_t smem_b = cvta_s(sm);

    // ---- B staging descriptors: 272 x 16B groups ----
    const float* bsrc0;
    uint32_t bdst0;
    {
        int run = tid / 17, q = tid - run * 17;
        int qe = (q > 15) ? 15 : q;    // clamp src; slots 64..67 garbage, never consumed
        int c2 = run >> 1, rr = run & 1;
        bsrc0 = x + ((size_t)(b * 64 + 2 * c2)) * 4096 + (ho0 + rr) * 64 + 4 * qe;
        bdst0 = (uint32_t)(AWRD + c2 * 136 + rr * 68 + 4 * q);
    }
    const float* bsrc1 = x;
    uint32_t bdst1 = 0;
    const bool has1 = (tid < 16);
    if (has1) {
        int i2 = 256 + tid;
        int run2 = i2 / 17, q2 = i2 - run2 * 17;
        int qe2 = (q2 > 15) ? 15 : q2;
        int c22 = run2 >> 1, r2 = run2 & 1;
        bsrc1 = x + ((size_t)(b * 64 + 2 * c22)) * 4096 + (ho0 + r2) * 64 + 4 * qe2;
        bdst1 = (uint32_t)(AWRD + c22 * 136 + r2 * 68 + 4 * q2);
    }

    float acc[2][4][4];
    #pragma unroll
    for (int mi = 0; mi < 2; ++mi)
        #pragma unroll
        for (int ni = 0; ni < 4; ++ni)
            #pragma unroll
            for (int q = 0; q < 4; ++q) acc[mi][ni][q] = 0.0f;

    const uint32_t a_fw = ((uint32_t)(woc * 32 + (lane >> 2)) * 8 + (lane & 3) * 2) * 4;
    const uint32_t b_fw = (uint32_t)(AWRD + (lane & 3) * 136 + rW * 68 + cW + (lane >> 2)) * 4;

    auto issueA = [&](int g, uint32_t bufw) {
        // 1536 words = 384 x 16B; 256 + 128 ops
        const uint4* asrc = (const uint4*)(g_a16 + (g * 2 + ocg) * AWRD) + tid;
        const uint32_t adst = smem_b + bufw * 4 + (uint32_t)tid * 16;
        CP_A16(adst, asrc);
        if (tid < 128) CP_A16(adst + 4096, asrc + 256);
        CP_COMMIT();
    };
    auto bSoff = [](int g) -> uint32_t {
        return (uint32_t)((g & 3) * 16 * 4096 + (g >> 2) * 64);   // floats
    };

    // ---- prologue ----
    issueA(0, 0);
    issueA(1, STW);
    {
        const uint32_t so = bSoff(0);
        float4 e0 = *(const float4*)(bsrc0 + so);
        float4 o0 = *(const float4*)(bsrc0 + so + 4096);
        uint4 v0;
        v0.x = pack_h2(e0.x, o0.x); v0.y = pack_h2(e0.y, o0.y);
        v0.z = pack_h2(e0.z, o0.z); v0.w = pack_h2(e0.w, o0.w);
        sts128(smem_b + bdst0 * 4, v0);
        if (has1) {
            float4 e1 = *(const float4*)(bsrc1 + so);
            float4 o1 = *(const float4*)(bsrc1 + so + 4096);
            uint4 v1;
            v1.x = pack_h2(e1.x, o1.x); v1.y = pack_h2(e1.y, o1.y);
            v1.z = pack_h2(e1.z, o1.z); v1.w = pack_h2(e1.w, o1.w);
            sts128(smem_b + bdst1 * 4, v1);
        }
    }

    uint32_t cbuf = 0;

    #pragma unroll 1
    for (int s = 0; s < 12; ++s) {
        if (s < 11) { CP_WAIT1(); } else { CP_WAIT0(); }
        __syncthreads();

        if (s + 2 < 12) {
            uint32_t b2 = cbuf + 2 * STW; if (b2 >= NBUF * STW) b2 -= NBUF * STW;
            issueA(s + 2, b2);
        }

        // B loads for next stage
        float4 e0, o0, e1, o1;
        const bool haveNext = (s + 1 < 12);
        if (haveNext) {
            const uint32_t so = bSoff(s + 1);
            e0 = *(const float4*)(bsrc0 + so);
            o0 = *(const float4*)(bsrc0 + so + 4096);
            if (has1) {
                e1 = *(const float4*)(bsrc1 + so);
                o1 = *(const float4*)(bsrc1 + so + 4096);
            }
        }

        // ---- compute stage s ----
        const uint32_t abase0 = smem_b + cbuf * 4 + a_fw;
        const uint32_t bbase0 = smem_b + cbuf * 4 + b_fw;

        #pragma unroll
        for (int kw = 0; kw < 3; ++kw) {
            const uint32_t abase = abase0 + (uint32_t)kw * 2048;   // 512 words per kw tile
            const uint32_t bbase = bbase0 + (uint32_t)kw * 4;

            uint32_t af[2][4], bf[4][2];
            #pragma unroll
            for (int mi = 0; mi < 2; ++mi) {
                uint2 t0 = lds64(abase + (uint32_t)mi * 512);
                uint2 t1 = lds64(abase + (uint32_t)(mi * 512 + 256));
                af[mi][0] = t0.x; af[mi][1] = t1.x; af[mi][2] = t0.y; af[mi][3] = t1.y;
            }
            #pragma unroll
            for (int ni = 0; ni < 4; ++ni) {
                bf[ni][0] = lds32(bbase + (uint32_t)ni * 32);
                bf[ni][1] = lds32(bbase + (uint32_t)ni * 32 + 2176);
            }
            #pragma unroll
            for (int mi = 0; mi < 2; ++mi)
                #pragma unroll
                for (int ni = 0; ni < 4; ++ni)
                    mma_f16(acc[mi][ni], af[mi], bf[ni]);
        }

        // ---- pack + store B(s+1) ----
        if (haveNext) {
            uint32_t nbuf = cbuf + STW; if (nbuf >= NBUF * STW) nbuf -= NBUF * STW;
            uint4 v0;
            v0.x = pack_h2(e0.x, o0.x); v0.y = pack_h2(e0.y, o0.y);
            v0.z = pack_h2(e0.z, o0.z); v0.w = pack_h2(e0.w, o0.w);
            sts128(smem_b + (nbuf + bdst0) * 4, v0);
            if (has1) {
                uint4 v1;
                v1.x = pack_h2(e1.x, o1.x); v1.y = pack_h2(e1.y, o1.y);
                v1.z = pack_h2(e1.z, o1.z); v1.w = pack_h2(e1.w, o1.w);
                sts128(smem_b + (nbuf + bdst1) * 4, v1);
            }
        }

        cbuf += STW; if (cbuf == NBUF * STW) cbuf = 0;
    }

    // ---- epilogue ----
    const int orow = ho0 + rW;
    #pragma unroll
    for (int mi = 0; mi < 2; ++mi) {
        #pragma unroll
        for (int ni = 0; ni < 4; ++ni) {
            const int ocr = ocg * 64 + woc * 32 + mi * 16 + (lane >> 2);
            const int wo  = cW + ni * 8 + 2 * (lane & 3);
            if (wo < WO) {
                const size_t base = (size_t)orow * WO + wo;
                float* p0 = out + ((size_t)ocr * NB + b) * NPB + base;
                *(float2*)p0 = make_float2(acc[mi][ni][0], acc[mi][ni][1]);
                float* p1 = out + ((size_t)(ocr + 8) * NB + b) * NPB + base;
                *(float2*)p1 = make_float2(acc[mi][ni][2], acc[mi][ni][3]);
            }
        }
    }
}

// ---------------- launch ----------------
extern "C" void kernel_launch(void* const* d_in, const int* in_sizes, int n_in,
                              void* d_out, int out_size) {
    const float* x = (const float*)d_in[0];
    const float* w = (const float*)d_in[1];
    float* out = (float*)d_out;

    prep_w<<<144, 256>>>(w);
    conv_main<<<dim3(62, NB), 256>>>(x, out);
}

// round 12
// speedup vs baseline: 1.2246x; 1.2246x over previous
#include <cuda_runtime.h>
#include <cstdint>

#define NB   32
#define NH   64
#define NW   64
#define HO   62
#define WO   62
#define NPB  (HO*WO)            // 3844

// A: [g 12][kw 3][oc 128][slot 8] fp16x2   (g = kh*4 + cblk)
__device__ __align__(16) uint32_t g_a16[36*1024];            // 147.5 KB

// ---- SMEM geometry (words per buffer) ----
#define AW1   3072              // one cblk: 3 kw x 128 oc x 8 slots
#define AWRD  6144              // two cblks
#define BW1   1088              // one cblk: 8 c2 x 2 rows x 68
#define BWRD  2176
#define STW   (AWRD + BWRD)     // 8320 words = 33280 B
#define NBUF  3
#define SMEMB (NBUF*STW*4)      // 99840 B

// ---------------- PTX helpers ----------------
__device__ __forceinline__ uint32_t cvta_s(const void* p) {
    uint32_t a;
    asm("{ .reg .u64 t; cvta.to.shared.u64 t, %1; cvt.u32.u64 %0, t; }" : "=r"(a) : "l"(p));
    return a;
}
__device__ __forceinline__ uint32_t pack_h2(float even, float odd) {
    uint32_t d;
    asm("cvt.rn.f16x2.f32 %0, %1, %2;" : "=r"(d) : "f"(odd), "f"(even));  // lo=even, hi=odd
    return d;
}
__device__ __forceinline__ uint2 lds64(uint32_t addr) {
    uint2 v;
    asm volatile("ld.shared.v2.b32 {%0,%1},[%2];" : "=r"(v.x), "=r"(v.y) : "r"(addr));
    return v;
}
__device__ __forceinline__ uint32_t lds32(uint32_t addr) {
    uint32_t v;
    asm volatile("ld.shared.b32 %0,[%1];" : "=r"(v) : "r"(addr));
    return v;
}
__device__ __forceinline__ void sts128(uint32_t addr, uint4 v) {
    asm volatile("st.shared.v4.b32 [%0],{%1,%2,%3,%4};"
                 :: "r"(addr), "r"(v.x), "r"(v.y), "r"(v.z), "r"(v.w) : "memory");
}
#define CP_A16(dst, src) asm volatile("cp.async.cg.shared.global [%0],[%1],16;" :: "r"(dst), "l"(src))
#define CP_COMMIT()      asm volatile("cp.async.commit_group;" ::: "memory")
#define CP_WAIT0()       asm volatile("cp.async.wait_group 0;" ::: "memory")
#define CP_WAIT1()       asm volatile("cp.async.wait_group 1;" ::: "memory")

__device__ __forceinline__ void mma_f16(float* c, const uint32_t* a, const uint32_t* b) {
    asm volatile(
        "mma.sync.aligned.m16n8k16.row.col.f32.f16.f16.f32 "
        "{%0,%1,%2,%3},{%4,%5,%6,%7},{%8,%9},{%0,%1,%2,%3};"
        : "+f"(c[0]), "+f"(c[1]), "+f"(c[2]), "+f"(c[3])
        : "r"(a[0]), "r"(a[1]), "r"(a[2]), "r"(a[3]), "r"(b[0]), "r"(b[1]));
}

// ---------------- prep kernel (weights only) ----------------
__global__ void prep_w(const float* __restrict__ w) {
    int idx = blockIdx.x * 256 + threadIdx.x;    // 36864
    int slot = idx & 7;
    int oc   = (idx >> 3) & 127;
    int sA   = idx >> 10;          // 0..35 = g*3 + kw
    int g    = sA / 3;
    int kw   = sA - g * 3;
    int kh   = g >> 2;
    int cblk = g & 3;
    int off  = kh * 3 + kw;
    int p    = (slot >> 1) + 4 * (slot & 1);
    int ce   = cblk * 16 + 2 * p;
    g_a16[idx] = pack_h2(w[oc * 576 + ce * 9 + off], w[oc * 576 + (ce + 1) * 9 + off]);
}

// ---------------- main kernel ----------------
// CTA: 128 oc x 2 rows x 64 wo; 6 mega-stages of K=96 (2 cblk).
__global__ __launch_bounds__(256, 2) void conv_main(const float* __restrict__ x,
                                                    float* __restrict__ out) {
    extern __shared__ __align__(16) uint32_t sm[];

    const int tid  = threadIdx.x;
    const int lane = tid & 31;
    const int warp = tid >> 5;
    const int wm   = warp >> 2;        // 0..1 : oc half
    const int wn   = warp & 3;
    const int rW   = wn >> 1;          // output row within pair
    const int cW   = (wn & 1) * 32;    // wo base

    const int b   = blockIdx.y;
    const int ho0 = blockIdx.x * 2;

    const uint32_t smem_b = cvta_s(sm);

    // ---- B staging descriptors (fp32 source, fp16 pack), per cblk sub-block ----
    const float* bsrc0;
    uint32_t bdst0;
    {
        int run = tid / 17, q = tid - run * 17;
        int qe = (q > 15) ? 15 : q;    // clamp src; slots 64..67 garbage, never consumed
        int c2 = run >> 1, rr = run & 1;
        bsrc0 = x + ((size_t)(b * 64 + 2 * c2)) * 4096 + (ho0 + rr) * 64 + 4 * qe;
        bdst0 = (uint32_t)(AWRD + c2 * 136 + rr * 68 + 4 * q);
    }
    const float* bsrc1 = x;
    uint32_t bdst1 = 0;
    const bool has1 = (tid < 16);
    if (has1) {
        int i2 = 256 + tid;
        int run2 = i2 / 17, q2 = i2 - run2 * 17;
        int qe2 = (q2 > 15) ? 15 : q2;
        int c22 = run2 >> 1, r2 = run2 & 1;
        bsrc1 = x + ((size_t)(b * 64 + 2 * c22)) * 4096 + (ho0 + r2) * 64 + 4 * qe2;
        bdst1 = (uint32_t)(AWRD + c22 * 136 + r2 * 68 + 4 * q2);
    }

    float acc[4][4][4];
    #pragma unroll
    for (int mi = 0; mi < 4; ++mi)
        #pragma unroll
        for (int ni = 0; ni < 4; ++ni)
            #pragma unroll
            for (int q = 0; q < 4; ++q) acc[mi][ni][q] = 0.0f;

    const uint32_t a_fw = ((uint32_t)(wm * 64 + (lane >> 2)) * 8 + (lane & 3) * 2) * 4;
    const uint32_t b_fw = (uint32_t)(AWRD + (lane & 3) * 136 + rW * 68 + cW + (lane >> 2)) * 4;

    // A for mega-stage m: g = 2m and 2m+1 (same kh, cblk pair)
    auto issueA = [&](int m, uint32_t bufw) {
        const uint4* asrc = (const uint4*)(g_a16 + 2 * m * AW1) + tid;
        const uint32_t adst = smem_b + bufw * 4 + (uint32_t)tid * 16;
        CP_A16(adst,         asrc);
        CP_A16(adst + 4096,  asrc + 256);
        CP_A16(adst + 8192,  asrc + 512);
        CP_A16(adst + 12288, asrc + 768);
        CP_A16(adst + 16384, asrc + 1024);
        CP_A16(adst + 20480, asrc + 1280);
        CP_COMMIT();
    };
    // source float offset for (mega m, sub): cblk = 2m+sub mod 4? g = 2m+sub
    auto bSoff = [](int m, int sub) -> uint32_t {
        int g = 2 * m + sub;
        return (uint32_t)((g & 3) * 16 * 4096 + (g >> 2) * 64);   // floats
    };

    // B LDG + pack + STS for (mega m, sub) into buffer bufw
    auto stageB = [&](int m, int sub, uint32_t bufw) {
        const uint32_t so = bSoff(m, sub);
        const uint32_t doff = (uint32_t)sub * BW1;
        float4 e0 = *(const float4*)(bsrc0 + so);
        float4 o0 = *(const float4*)(bsrc0 + so + 4096);
        uint4 v0;
        v0.x = pack_h2(e0.x, o0.x); v0.y = pack_h2(e0.y, o0.y);
        v0.z = pack_h2(e0.z, o0.z); v0.w = pack_h2(e0.w, o0.w);
        sts128(smem_b + (bufw + doff + bdst0) * 4, v0);
        if (has1) {
            float4 e1 = *(const float4*)(bsrc1 + so);
            float4 o1 = *(const float4*)(bsrc1 + so + 4096);
            uint4 v1;
            v1.x = pack_h2(e1.x, o1.x); v1.y = pack_h2(e1.y, o1.y);
            v1.z = pack_h2(e1.z, o1.z); v1.w = pack_h2(e1.w, o1.w);
            sts128(smem_b + (bufw + doff + bdst1) * 4, v1);
        }
    };

    // compute one cblk sub-block (3 kw x 16 HMMA)
    auto computeSub = [&](uint32_t bufw, int sub) {
        const uint32_t abase0 = smem_b + (bufw + (uint32_t)sub * AW1) * 4 + a_fw;
        const uint32_t bbase0 = smem_b + (bufw + (uint32_t)sub * BW1) * 4 + b_fw;
        #pragma unroll
        for (int kw = 0; kw < 3; ++kw) {
            const uint32_t abase = abase0 + (uint32_t)kw * 4096;
            const uint32_t bbase = bbase0 + (uint32_t)kw * 4;
            uint32_t af[4][4], bf[4][2];
            #pragma unroll
            for (int mi = 0; mi < 4; ++mi) {
                uint2 t0 = lds64(abase + (uint32_t)mi * 512);
                uint2 t1 = lds64(abase + (uint32_t)(mi * 512 + 256));
                af[mi][0] = t0.x; af[mi][1] = t1.x; af[mi][2] = t0.y; af[mi][3] = t1.y;
            }
            #pragma unroll
            for (int ni = 0; ni < 4; ++ni) {
                bf[ni][0] = lds32(bbase + (uint32_t)ni * 32);
                bf[ni][1] = lds32(bbase + (uint32_t)ni * 32 + 2176);
            }
            #pragma unroll
            for (int mi = 0; mi < 4; ++mi)
                #pragma unroll
                for (int ni = 0; ni < 4; ++ni)
                    mma_f16(acc[mi][ni], af[mi], bf[ni]);
        }
    };

    // ---- prologue: A(0), A(1) async; B(0) both subs direct ----
    issueA(0, 0);
    issueA(1, STW);
    stageB(0, 0, 0);
    stageB(0, 1, 0);

    uint32_t cbuf = 0;

    #pragma unroll 1
    for (int s = 0; s < 6; ++s) {
        if (s < 5) { CP_WAIT1(); } else { CP_WAIT0(); }
        __syncthreads();

        if (s + 2 < 6) {
            uint32_t b2 = cbuf + 2 * STW; if (b2 >= NBUF * STW) b2 -= NBUF * STW;
            issueA(s + 2, b2);
        }
        uint32_t nbuf = cbuf + STW; if (nbuf >= NBUF * STW) nbuf -= NBUF * STW;
        const bool haveNext = (s + 1 < 6);

        // LDG for next-stage sub0 issued here, hidden under sub0 compute
        float4 e0, o0, e1, o1;
        if (haveNext) {
            const uint32_t so = bSoff(s + 1, 0);
            e0 = *(const float4*)(bsrc0 + so);
            o0 = *(const float4*)(bsrc0 + so + 4096);
            if (has1) { e1 = *(const float4*)(bsrc1 + so);
                        o1 = *(const float4*)(bsrc1 + so + 4096); }
        }

        computeSub(cbuf, 0);

        if (haveNext) {
            uint4 v0;
            v0.x = pack_h2(e0.x, o0.x); v0.y = pack_h2(e0.y, o0.y);
            v0.z = pack_h2(e0.z, o0.z); v0.w = pack_h2(e0.w, o0.w);
            sts128(smem_b + (nbuf + bdst0) * 4, v0);
            if (has1) {
                uint4 v1;
                v1.x = pack_h2(e1.x, o1.x); v1.y = pack_h2(e1.y, o1.y);
                v1.z = pack_h2(e1.z, o1.z); v1.w = pack_h2(e1.w, o1.w);
                sts128(smem_b + (nbuf + bdst1) * 4, v1);
            }
            // LDG for next-stage sub1, hidden under sub1 compute
            const uint32_t so = bSoff(s + 1, 1);
            e0 = *(const float4*)(bsrc0 + so);
            o0 = *(const float4*)(bsrc0 + so + 4096);
            if (has1) { e1 = *(const float4*)(bsrc1 + so);
                        o1 = *(const float4*)(bsrc1 + so + 4096); }
        }

        computeSub(cbuf, 1);

        if (haveNext) {
            uint4 v0;
            v0.x = pack_h2(e0.x, o0.x); v0.y = pack_h2(e0.y, o0.y);
            v0.z = pack_h2(e0.z, o0.z); v0.w = pack_h2(e0.w, o0.w);
            sts128(smem_b + (nbuf + BW1 + bdst0) * 4, v0);
            if (has1) {
                uint4 v1;
                v1.x = pack_h2(e1.x, o1.x); v1.y = pack_h2(e1.y, o1.y);
                v1.z = pack_h2(e1.z, o1.z); v1.w = pack_h2(e1.w, o1.w);
                sts128(smem_b + (nbuf + BW1 + bdst1) * 4, v1);
            }
        }

        cbuf = nbuf;
    }

    // ---- epilogue ----
    const int orow = ho0 + rW;
    #pragma unroll
    for (int mi = 0; mi < 4; ++mi) {
        #pragma unroll
        for (int ni = 0; ni < 4; ++ni) {
            const int ocr = wm * 64 + mi * 16 + (lane >> 2);
            const int wo  = cW + ni * 8 + 2 * (lane & 3);
            if (wo < WO) {
                const size_t base = (size_t)orow * WO + wo;
                float* p0 = out + ((size_t)ocr * NB + b) * NPB + base;
                *(float2*)p0 = make_float2(acc[mi][ni][0], acc[mi][ni][1]);
                float* p1 = out + ((size_t)(ocr + 8) * NB + b) * NPB + base;
                *(float2*)p1 = make_float2(acc[mi][ni][2], acc[mi][ni][3]);
            }
        }
    }
}

// ---------------- launch ----------------
extern "C" void kernel_launch(void* const* d_in, const int* in_sizes, int n_in,
                              void* d_out, int out_size) {
    const float* x = (const float*)d_in[0];
    const float* w = (const float*)d_in[1];
    float* out = (float*)d_out;

    cudaFuncSetAttribute(conv_main, cudaFuncAttributeMaxDynamicSharedMemorySize, SMEMB);

    prep_w<<<144, 256>>>(w);
    conv_main<<<dim3(31, NB), 256, SMEMB>>>(x, out);
}

// round 13
// speedup vs baseline: 1.3047x; 1.0654x over previous
#include <cuda_runtime.h>
#include <cstdint>

#define NB   32
#define NH   64
#define NW   64
#define HO   62
#define WO   62
#define NPB  (HO*WO)            // 3844

// A: [cblk 4][kh 3][kw 3][oc 128][slot 8] fp16x2
__device__ __align__(16) uint32_t g_a16[36*1024];            // 147.5 KB

// ---- SMEM geometry (words per buffer) ----
#define AWRD  9216              // 9 (kh,kw) tiles x 128 oc x 8 slots
#define BROWW 72                // B words per c2 row (68 data + 4 pad)
#define BWRD  (4*8*BROWW)       // 2304 : [row 4][c2 8][72]
#define STW   (AWRD + BWRD)     // 11520
#define NBUF  2
#define SMEMB (NBUF*STW*4)      // 92160 B

// ---------------- PTX helpers ----------------
__device__ __forceinline__ uint32_t cvta_s(const void* p) {
    uint32_t a;
    asm("{ .reg .u64 t; cvta.to.shared.u64 t, %1; cvt.u32.u64 %0, t; }" : "=r"(a) : "l"(p));
    return a;
}
__device__ __forceinline__ uint32_t pack_h2(float even, float odd) {
    uint32_t d;
    asm("cvt.rn.f16x2.f32 %0, %1, %2;" : "=r"(d) : "f"(odd), "f"(even));  // lo=even, hi=odd
    return d;
}
__device__ __forceinline__ uint2 lds64(uint32_t addr) {
    uint2 v;
    asm volatile("ld.shared.v2.b32 {%0,%1},[%2];" : "=r"(v.x), "=r"(v.y) : "r"(addr));
    return v;
}
__device__ __forceinline__ uint32_t lds32(uint32_t addr) {
    uint32_t v;
    asm volatile("ld.shared.b32 %0,[%1];" : "=r"(v) : "r"(addr));
    return v;
}
__device__ __forceinline__ void sts128(uint32_t addr, uint4 v) {
    asm volatile("st.shared.v4.b32 [%0],{%1,%2,%3,%4};"
                 :: "r"(addr), "r"(v.x), "r"(v.y), "r"(v.z), "r"(v.w) : "memory");
}
#define CP_A16(dst, src) asm volatile("cp.async.cg.shared.global [%0],[%1],16;" :: "r"(dst), "l"(src))
#define CP_COMMIT()      asm volatile("cp.async.commit_group;" ::: "memory")
#define CP_WAIT0()       asm volatile("cp.async.wait_group 0;" ::: "memory")

__device__ __forceinline__ void mma_f16(float* c, const uint32_t* a, const uint32_t* b) {
    asm volatile(
        "mma.sync.aligned.m16n8k16.row.col.f32.f16.f16.f32 "
        "{%0,%1,%2,%3},{%4,%5,%6,%7},{%8,%9},{%0,%1,%2,%3};"
        : "+f"(c[0]), "+f"(c[1]), "+f"(c[2]), "+f"(c[3])
        : "r"(a[0]), "r"(a[1]), "r"(a[2]), "r"(a[3]), "r"(b[0]), "r"(b[1]));
}

// ---------------- prep kernel (weights only) ----------------
// idx = ((((cblk*3 + kh)*3 + kw)*128 + oc)*8 + slot)
__global__ void prep_w(const float* __restrict__ w) {
    int idx = blockIdx.x * 256 + threadIdx.x;    // 36864
    int slot = idx & 7;
    int oc   = (idx >> 3) & 127;
    int t    = idx >> 10;          // 0..35
    int cblk = t / 9;
    int r9   = t - cblk * 9;
    int kh   = r9 / 3;
    int kw   = r9 - kh * 3;
    int off  = kh * 3 + kw;
    int p    = (slot >> 1) + 4 * (slot & 1);
    int ce   = cblk * 16 + 2 * p;
    g_a16[idx] = pack_h2(w[oc * 576 + ce * 9 + off], w[oc * 576 + (ce + 1) * 9 + off]);
}

// ---------------- main kernel ----------------
// CTA: 128 oc x 2 out-rows x 64 wo; 4 stages (one per cblk, K=144).
__global__ __launch_bounds__(256, 2) void conv_main(const float* __restrict__ x,
                                                    float* __restrict__ out) {
    extern __shared__ __align__(16) uint32_t sm[];

    const int tid  = threadIdx.x;
    const int lane = tid & 31;
    const int warp = tid >> 5;
    const int wm   = warp >> 2;        // 0..1 : oc half
    const int wn   = warp & 3;
    const int rW   = wn >> 1;          // output row within pair
    const int cW   = (wn & 1) * 32;    // wo base

    const int b   = blockIdx.y;
    const int ho0 = blockIdx.x * 2;

    const uint32_t smem_b = cvta_s(sm);

    // ---- B staging descriptors: 544 x 16B ops; op e: r=e/17 (0..31), q=e%17 ----
    //   r: c2 = r>>2, row = r&3 ; dst word = row*576 + c2*72 + 4q (within B region)
    //   src = x + (b*64 + 2*c2)*4096 + (ho0+row)*64 + 4*min(q,15)   (+stage cblk offs)
    const float* bs[3]; uint32_t bdw[3]; bool bact[3];
    #pragma unroll
    for (int j = 0; j < 3; ++j) {
        int e = tid + j * 256;
        bact[j] = (e < 544);
        int ee = bact[j] ? e : 0;
        int r  = ee / 17, q = ee - r * 17;
        int qe = (q > 15) ? 15 : q;
        int c2 = r >> 2, row = r & 3;
        bs[j]  = x + ((size_t)(b * 64 + 2 * c2)) * 4096 + (ho0 + row) * 64 + 4 * qe;
        bdw[j] = (uint32_t)(AWRD + row * (8 * BROWW) + c2 * BROWW + 4 * q);
    }

    float acc[4][4][4];
    #pragma unroll
    for (int mi = 0; mi < 4; ++mi)
        #pragma unroll
        for (int ni = 0; ni < 4; ++ni)
            #pragma unroll
            for (int q = 0; q < 4; ++q) acc[mi][ni][q] = 0.0f;

    const uint32_t a_fw = ((uint32_t)(wm * 64 + (lane >> 2)) * 8 + (lane & 3) * 2) * 4;
    // B fragment base: row selected per kh; here the static part
    const uint32_t b_fw = (uint32_t)(AWRD + (lane & 3) * BROWW + cW + (lane >> 2)) * 4;

    auto issueA = [&](int cblk, uint32_t bufw) {
        const uint4* asrc = (const uint4*)(g_a16 + cblk * AWRD) + tid;
        uint32_t adst = smem_b + bufw * 4 + (uint32_t)tid * 16;
        #pragma unroll
        for (int j = 0; j < 9; ++j)
            CP_A16(adst + (uint32_t)j * 4096, asrc + j * 256);
        CP_COMMIT();
    };

    // ---- prologue: A(0) async; B(0) direct ----
    issueA(0, 0);
    #pragma unroll
    for (int j = 0; j < 3; ++j) {
        if (bact[j]) {
            float4 e = *(const float4*)(bs[j]);
            float4 o = *(const float4*)(bs[j] + 4096);
            uint4 v;
            v.x = pack_h2(e.x, o.x); v.y = pack_h2(e.y, o.y);
            v.z = pack_h2(e.z, o.z); v.w = pack_h2(e.w, o.w);
            sts128(smem_b + bdw[j] * 4, v);
        }
    }

    uint32_t cbuf = 0;

    #pragma unroll 1
    for (int s = 0; s < 4; ++s) {
        CP_WAIT0();
        __syncthreads();

        const uint32_t nbuf = cbuf ^ STW;
        const bool haveNext = (s + 1 < 4);
        if (haveNext) issueA(s + 1, nbuf);

        const uint32_t nso = (uint32_t)((s + 1) * 16 * 4096);   // next-stage src float offset

        const uint32_t abase0 = smem_b + cbuf * 4 + a_fw;
        const uint32_t bbaseS = smem_b + cbuf * 4 + b_fw;

        #pragma unroll
        for (int kh = 0; kh < 3; ++kh) {
            // LDG for next-stage B op #kh (hidden under this kh's compute)
            float4 e, o;
            const bool doB = haveNext && bact[kh];
            if (doB) {
                e = *(const float4*)(bs[kh] + nso);
                o = *(const float4*)(bs[kh] + nso + 4096);
            }

            const uint32_t brow = bbaseS + (uint32_t)((rW + kh) * (8 * BROWW)) * 4;
            #pragma unroll
            for (int kw = 0; kw < 3; ++kw) {
                const uint32_t abase = abase0 + (uint32_t)(kh * 3 + kw) * 4096;
                const uint32_t bbase = brow + (uint32_t)kw * 4;

                uint32_t af[4][4], bf[4][2];
                #pragma unroll
                for (int mi = 0; mi < 4; ++mi) {
                    uint2 t0 = lds64(abase + (uint32_t)mi * 512);
                    uint2 t1 = lds64(abase + (uint32_t)(mi * 512 + 256));
                    af[mi][0] = t0.x; af[mi][1] = t1.x; af[mi][2] = t0.y; af[mi][3] = t1.y;
                }
                #pragma unroll
                for (int ni = 0; ni < 4; ++ni) {
                    bf[ni][0] = lds32(bbase + (uint32_t)ni * 32);
                    bf[ni][1] = lds32(bbase + (uint32_t)ni * 32 + 4 * BROWW * 4);
                }
                #pragma unroll
                for (int mi = 0; mi < 4; ++mi)
                    #pragma unroll
                    for (int ni = 0; ni < 4; ++ni)
                        mma_f16(acc[mi][ni], af[mi], bf[ni]);
            }

            // pack + store next-stage B op #kh into nbuf
            if (doB) {
                uint4 v;
                v.x = pack_h2(e.x, o.x); v.y = pack_h2(e.y, o.y);
                v.z = pack_h2(e.z, o.z); v.w = pack_h2(e.w, o.w);
                sts128(smem_b + (nbuf + bdw[kh]) * 4, v);
            }
        }

        cbuf = nbuf;
    }

    // ---- epilogue ----
    const int orow = ho0 + rW;
    #pragma unroll
    for (int mi = 0; mi < 4; ++mi) {
        #pragma unroll
        for (int ni = 0; ni < 4; ++ni) {
            const int ocr = wm * 64 + mi * 16 + (lane >> 2);
            const int wo  = cW + ni * 8 + 2 * (lane & 3);
            if (wo < WO) {
                const size_t base = (size_t)orow * WO + wo;
                float* p0 = out + ((size_t)ocr * NB + b) * NPB + base;
                *(float2*)p0 = make_float2(acc[mi][ni][0], acc[mi][ni][1]);
                float* p1 = out + ((size_t)(ocr + 8) * NB + b) * NPB + base;
                *(float2*)p1 = make_float2(acc[mi][ni][2], acc[mi][ni][3]);
            }
        }
    }
}

// ---------------- launch ----------------
extern "C" void kernel_launch(void* const* d_in, const int* in_sizes, int n_in,
                              void* d_out, int out_size) {
    const float* x = (const float*)d_in[0];
    const float* w = (const float*)d_in[1];
    float* out = (float*)d_out;

    cudaFuncSetAttribute(conv_main, cudaFuncAttributeMaxDynamicSharedMemorySize, SMEMB);

    prep_w<<<144, 256>>>(w);
    conv_main<<<dim3(31, NB), 256, SMEMB>>>(x, out);
}

// round 15
// speedup vs baseline: 1.3425x; 1.0289x over previous
#include <cuda_runtime.h>
#include <cstdint>

#define NB   32
#define NH   64
#define NW   64
#define HO   62
#define WO   62
#define NPB  (HO*WO)            // 3844

// A: [cblk 4][kh 3][kw 3][ocb 8][perm 128] fp16x2 (lane-major permuted layout)
__device__ __align__(16) uint32_t g_a16[36*1024];            // 147.5 KB

// ---- SMEM geometry (words per buffer) ----
#define AWRD  9216              // 9 (kh,kw) tiles x 1024 words
#define BROWW 72                // B words per c2 row (68 data + 4 pad)
#define BWRD  (4*8*BROWW)       // 2304 : [row 4][c2 8][72]
#define STW   (AWRD + BWRD)     // 11520
#define NBUF  2
#define SMEMB (NBUF*STW*4)      // 92160 B

// ---------------- PTX helpers ----------------
__device__ __forceinline__ uint32_t cvta_s(const void* p) {
    uint32_t a;
    asm("{ .reg .u64 t; cvta.to.shared.u64 t, %1; cvt.u32.u64 %0, t; }" : "=r"(a) : "l"(p));
    return a;
}
__device__ __forceinline__ uint32_t pack_h2(float even, float odd) {
    uint32_t d;
    asm("cvt.rn.f16x2.f32 %0, %1, %2;" : "=r"(d) : "f"(odd), "f"(even));  // lo=even, hi=odd
    return d;
}
__device__ __forceinline__ uint32_t lds32(uint32_t addr) {
    uint32_t v;
    asm volatile("ld.shared.b32 %0,[%1];" : "=r"(v) : "r"(addr));
    return v;
}
__device__ __forceinline__ uint4 lds128(uint32_t addr) {
    uint4 v;
    asm volatile("ld.shared.v4.b32 {%0,%1,%2,%3},[%4];"
                 : "=r"(v.x), "=r"(v.y), "=r"(v.z), "=r"(v.w) : "r"(addr));
    return v;
}
__device__ __forceinline__ void sts128(uint32_t addr, uint4 v) {
    asm volatile("st.shared.v4.b32 [%0],{%1,%2,%3,%4};"
                 :: "r"(addr), "r"(v.x), "r"(v.y), "r"(v.z), "r"(v.w) : "memory");
}
#define CP_A16(dst, src) asm volatile("cp.async.cg.shared.global [%0],[%1],16;" :: "r"(dst), "l"(src))
#define CP_COMMIT()      asm volatile("cp.async.commit_group;" ::: "memory")
#define CP_WAIT0()       asm volatile("cp.async.wait_group 0;" ::: "memory")

__device__ __forceinline__ void mma_f16(float* c, const uint32_t* a, uint32_t b0, uint32_t b1) {
    asm volatile(
        "mma.sync.aligned.m16n8k16.row.col.f32.f16.f16.f32 "
        "{%0,%1,%2,%3},{%4,%5,%6,%7},{%8,%9},{%0,%1,%2,%3};"
        : "+f"(c[0]), "+f"(c[1]), "+f"(c[2]), "+f"(c[3])
        : "r"(a[0]), "r"(a[1]), "r"(a[2]), "r"(a[3]), "r"(b0), "r"(b1));
}

// ---------------- prep kernel (weights only) ----------------
// A tile (cblk,kh,kw) = 1024 words; within: ocb = (oc>>4) block of 128 words,
// permuted so lane l's four fragment words (a0..a3) sit at l*4..l*4+3.
__global__ void prep_w(const float* __restrict__ w) {
    int idx = blockIdx.x * 256 + threadIdx.x;    // 36864 (cblk,kh,kw,oc,slot)
    int slot = idx & 7;
    int oc   = (idx >> 3) & 127;
    int t    = idx >> 10;          // 0..35
    int cblk = t / 9;
    int r9   = t - cblk * 9;
    int kh   = r9 / 3;
    int kw   = r9 - kh * 3;
    int off  = kh * 3 + kw;
    int p    = (slot >> 1) + 4 * (slot & 1);
    int ce   = cblk * 16 + 2 * p;
    uint32_t val = pack_h2(w[oc * 576 + ce * 9 + off], w[oc * 576 + (ce + 1) * 9 + off]);

    int ocb = oc >> 4;
    int ocr = oc & 15;
    int r8  = ocr & 7;
    int hi  = ocr >> 3;
    int n   = (r8 * 4 + (slot >> 1)) * 4 + (slot & 1) * 2 + hi;
    g_a16[t * 1024 + ocb * 128 + n] = val;
}

// ---------------- main kernel ----------------
// CTA: 128 oc x 2 out-rows x 64 wo; 4 stages (one per cblk, K=144).
__global__ __launch_bounds__(256, 2) void conv_main(const float* __restrict__ x,
                                                    float* __restrict__ out) {
    extern __shared__ __align__(16) uint32_t sm[];

    const int tid  = threadIdx.x;
    const int lane = tid & 31;
    const int warp = tid >> 5;
    const int wm   = warp >> 2;        // 0..1 : oc half
    const int wn   = warp & 3;
    const int rW   = wn >> 1;          // output row within pair
    const int cW   = (wn & 1) * 32;    // wo base

    const int b   = blockIdx.y;
    const int ho0 = blockIdx.x * 2;

    const uint32_t smem_b = cvta_s(sm);

    // ---- B staging descriptors: 544 x 16B ops ----
    const float* bs[3]; uint32_t bdw[3]; bool bact[3];
    #pragma unroll
    for (int j = 0; j < 3; ++j) {
        int e = tid + j * 256;
        bact[j] = (e < 544);
        int ee = bact[j] ? e : 0;
        int r  = ee / 17, q = ee - r * 17;
        int qe = (q > 15) ? 15 : q;
        int c2 = r >> 2, row = r & 3;
        bs[j]  = x + ((size_t)(b * 64 + 2 * c2)) * 4096 + (ho0 + row) * 64 + 4 * qe;
        bdw[j] = (uint32_t)(AWRD + row * (8 * BROWW) + c2 * BROWW + 4 * q);
    }

    float acc[4][4][4];
    #pragma unroll
    for (int mi = 0; mi < 4; ++mi)
        #pragma unroll
        for (int ni = 0; ni < 4; ++ni)
            #pragma unroll
            for (int q = 0; q < 4; ++q) acc[mi][ni][q] = 0.0f;

    // A fragment base: wm block (4 mi-tiles of 128 words) + lane*4 words (16B aligned)
    const uint32_t a_fw = (uint32_t)(wm * 512 + lane * 4) * 4;
    const uint32_t b_fw = (uint32_t)(AWRD + (lane & 3) * BROWW + cW + (lane >> 2)) * 4;

    auto issueA = [&](int cblk, uint32_t bufw) {
        const uint4* asrc = (const uint4*)(g_a16 + cblk * AWRD) + tid;
        uint32_t adst = smem_b + bufw * 4 + (uint32_t)tid * 16;
        #pragma unroll
        for (int j = 0; j < 9; ++j)
            CP_A16(adst + (uint32_t)j * 4096, asrc + j * 256);
        CP_COMMIT();
    };

    // ---- prologue ----
    issueA(0, 0);
    #pragma unroll
    for (int j = 0; j < 3; ++j) {
        if (bact[j]) {
            float4 e = *(const float4*)(bs[j]);
            float4 o = *(const float4*)(bs[j] + 4096);
            uint4 v;
            v.x = pack_h2(e.x, o.x); v.y = pack_h2(e.y, o.y);
            v.z = pack_h2(e.z, o.z); v.w = pack_h2(e.w, o.w);
            sts128(smem_b + bdw[j] * 4, v);
        }
    }

    uint32_t cbuf = 0;

    #pragma unroll 1
    for (int s = 0; s < 4; ++s) {
        CP_WAIT0();
        __syncthreads();

        const uint32_t nbuf = cbuf ^ STW;
        const bool haveNext = (s + 1 < 4);
        if (haveNext) issueA(s + 1, nbuf);

        const uint32_t nso = (uint32_t)((s + 1) * 16 * 4096);

        const uint32_t abase0 = smem_b + cbuf * 4 + a_fw;
        const uint32_t bbaseS = smem_b + cbuf * 4 + b_fw;

        #pragma unroll
        for (int ki = 0; ki < 3; ++ki) {
            // stagger: wm=1 warps walk kh (and kw) reversed
            const int kh = wm ? (2 - ki) : ki;

            // next-stage B LDG (keyed to loop index, hidden under compute)
            float4 e, o;
            const bool doB = haveNext && bact[ki];
            if (doB) {
                e = *(const float4*)(bs[ki] + nso);
                o = *(const float4*)(bs[ki] + nso + 4096);
            }

            const uint32_t brow = bbaseS + (uint32_t)((rW + kh) * (8 * BROWW)) * 4;

            #pragma unroll
            for (int kj = 0; kj < 3; ++kj) {
                const int kw = wm ? (2 - kj) : kj;
                const uint32_t abase = abase0 + (uint32_t)(kh * 3 + kw) * 4096;
                const uint32_t bbase = brow + (uint32_t)kw * 4;

                uint32_t bf[4][2];
                #pragma unroll
                for (int ni = 0; ni < 4; ++ni) {
                    bf[ni][0] = lds32(bbase + (uint32_t)ni * 32);
                    bf[ni][1] = lds32(bbase + (uint32_t)ni * 32 + 4 * BROWW * 4);
                }
                #pragma unroll
                for (int mi = 0; mi < 4; ++mi) {
                    uint4 a4 = lds128(abase + (uint32_t)mi * 512);
                    uint32_t af[4] = {a4.x, a4.y, a4.z, a4.w};
                    #pragma unroll
                    for (int ni = 0; ni < 4; ++ni)
                        mma_f16(acc[mi][ni], af, bf[ni][0], bf[ni][1]);
                }
            }

            if (doB) {
                uint4 v;
                v.x = pack_h2(e.x, o.x); v.y = pack_h2(e.y, o.y);
                v.z = pack_h2(e.z, o.z); v.w = pack_h2(e.w, o.w);
                sts128(smem_b + (nbuf + bdw[ki]) * 4, v);
            }
        }

        cbuf = nbuf;
    }

    // ---- epilogue ----
    const int orow = ho0 + rW;
    #pragma unroll
    for (int mi = 0; mi < 4; ++mi) {
        #pragma unroll
        for (int ni = 0; ni < 4; ++ni) {
            const int ocr = wm * 64 + mi * 16 + (lane >> 2);
            const int wo  = cW + ni * 8 + 2 * (lane & 3);
            if (wo < WO) {
                const size_t base = (size_t)orow * WO + wo;
                float* p0 = out + ((size_t)ocr * NB + b) * NPB + base;
                *(float2*)p0 = make_float2(acc[mi][ni][0], acc[mi][ni][1]);
                float* p1 = out + ((size_t)(ocr + 8) * NB + b) * NPB + base;
                *(float2*)p1 = make_float2(acc[mi][ni][2], acc[mi][ni][3]);
            }
        }
    }
}

// ---------------- launch ----------------
extern "C" void kernel_launch(void* const* d_in, const int* in_sizes, int n_in,
                              void* d_out, int out_size) {
    const float* x = (const float*)d_in[0];
    const float* w = (const float*)d_in[1];
    float* out = (float*)d_out;

    cudaFuncSetAttribute(conv_main, cudaFuncAttributeMaxDynamicSharedMemorySize, SMEMB);

    prep_w<<<144, 256>>>(w);
    conv_main<<<dim3(31, NB), 256, SMEMB>>>(x, out);
}